// round 1
// baseline (speedup 1.0000x reference)
#include <cuda_runtime.h>

// DifferentialNoise: x shape [128,64,64,64] fp32, flattened into pairs (a,b).
// out_even = a; out_odd = b - a/50.
// Pure streaming elementwise: 128 MiB in + 128 MiB out -> HBM-bound.
// Process as float4 (two pairs per thread) for 16B coalesced LDG/STG.

__global__ void __launch_bounds__(256) diff_noise_kernel(
    const float4* __restrict__ in, float4* __restrict__ out, int n4)
{
    int i = blockIdx.x * blockDim.x + threadIdx.x;
    if (i < n4) {
        float4 v = in[i];
        // pairs: (x,y) and (z,w)
        v.y = fmaf(v.x, -0.02f, v.y);  // y - x/50
        v.w = fmaf(v.z, -0.02f, v.w);  // w - z/50
        out[i] = v;
    }
}

extern "C" void kernel_launch(void* const* d_in, const int* in_sizes, int n_in,
                              void* d_out, int out_size)
{
    const float4* in = (const float4*)d_in[0];
    float4* out = (float4*)d_out;
    int n = in_sizes[0];        // 33,554,432 elements
    int n4 = n >> 2;            // 8,388,608 float4s (n divisible by 4: W*H=4096)
    int threads = 256;
    int blocks = (n4 + threads - 1) / threads;
    diff_noise_kernel<<<blocks, threads>>>(in, out, n4);
}